// round 15
// baseline (speedup 1.0000x reference)
#include <cuda_runtime.h>

#define NN   128
#define BB   32
#define INF  4608
#define KSPLIT 36    // 4608 / 128
#define KSEG   128

// ---------------- device scratch ----------------
__device__ float g_qsum[NN];              // qsum[i] = sum_n Q[n][i]
__device__ float g_q127[NN];              // q127[n] = Q[n][127]
__device__ float g_nsum[NN];              // nsum[d] = sum_n ns[n][d]
__device__ float g_P[KSPLIT * BB * NN];   // split-K partials of x @ Wt
__device__ float g_M0T[NN * NN];          // M0T[i][d] = sum_n ns[n][d] Q[n][i]
__device__ float g_out[BB * NN];          // out[b][d]

// ---------------- K1 (fused): ev-reduce -> qsum/q127/M0T ; nsum ; input GEMM ----------------
__global__ void __launch_bounds__(256) k_fused1(const float* __restrict__ ev,
                                                const float* __restrict__ ns,
                                                const float* __restrict__ x,
                                                const float* __restrict__ w) {
    int bi = blockIdx.x;
    int t  = threadIdx.x;
    if (bi < NN) {
        // ---- per-i: qv[n] = Q[n][i] = sum_j ev[i][j][n] (float4 over n) ----  [R9 form]
        __shared__ float4 sred[256];
        __shared__ float  qsh[NN];
        __shared__ float  pd[256];
        int i  = bi;
        int n4 = t & 31;            // float4 index over n (32 x 4 = 128)
        int j0 = t >> 5;            // 0..7
        const float4* p4 = (const float4*)(ev + (size_t)i * NN * NN);  // [128][32]
        float4 a = make_float4(0.f, 0.f, 0.f, 0.f);
        #pragma unroll
        for (int j = j0; j < NN; j += 8) {
            float4 v = p4[j * 32 + n4];
            a.x += v.x; a.y += v.y; a.z += v.z; a.w += v.w;
        }
        sred[t] = a;
        __syncthreads();
        if (j0 < 4) {
            float4 b = sred[t + 128];
            a.x += b.x; a.y += b.y; a.z += b.z; a.w += b.w;
            sred[t] = a;
        }
        __syncthreads();
        if (j0 < 2) {
            float4 b = sred[t + 64];
            a.x += b.x; a.y += b.y; a.z += b.z; a.w += b.w;
            sred[t] = a;
        }
        __syncthreads();
        if (j0 == 0) {
            float4 b = sred[t + 32];
            a.x += b.x; a.y += b.y; a.z += b.z; a.w += b.w;
            qsh[4 * n4 + 0] = a.x; qsh[4 * n4 + 1] = a.y;
            qsh[4 * n4 + 2] = a.z; qsh[4 * n4 + 3] = a.w;
            if (i == 127) ((float4*)g_q127)[n4] = a;       // Q[n][127]
            float s = a.x + a.y + a.z + a.w;
            #pragma unroll
            for (int off = 16; off > 0; off >>= 1)
                s += __shfl_xor_sync(0xffffffffu, s, off);
            if (n4 == 0) g_qsum[i] = s;
        }
        __syncthreads();
        // M0T[i][d] = sum_n qsh[n] * ns[n][d]  (split n across 2 halves)
        int d = t & 127, h = t >> 7;
        float m = 0.f;
        int nb = h * 64;
        #pragma unroll 8
        for (int k = 0; k < 64; k++) m += qsh[nb + k] * ns[(nb + k) * NN + d];
        pd[t] = m;
        __syncthreads();
        if (t < NN) g_M0T[i * NN + t] = pd[t] + pd[t + 128];
    } else if (bi == NN) {
        // ---- nsum[d] = sum_n ns[n][d] ----
        if (t < NN) {
            float acc = 0.f;
            #pragma unroll 16
            for (int n = 0; n < NN; n++) acc += ns[n * NN + t];
            g_nsum[t] = acc;
        }
    } else {
        // ---- input GEMM split-K, k-major float4 tiles, 2x2 register tiling ----
        __shared__ float4 xs4[32 * 33];   // xs4[b][k4], pad 33
        __shared__ float4 ws4[32 * 33];   // ws4[dl][k4], pad 33
        int idx = bi - NN - 1;
        int s   = idx >> 2;          // 0..35
        int db  = idx & 3;           // 0..3
        int k0  = s * KSEG;
        int d0  = db * 32;
        // stage 32 rows x 32 f4, k-major (rows are k-contiguous in gmem)
        #pragma unroll
        for (int it = 0; it < 4; it++) {
            int e  = t + it * 256;
            int r  = e >> 5, c4 = e & 31;
            xs4[r * 33 + c4] = *(const float4*)&x[r * INF + k0 + c4 * 4];
            ws4[r * 33 + c4] = *(const float4*)&w[(d0 + r) * INF + k0 + c4 * 4];
        }
        __syncthreads();
        int bq = t & 15;             // b in {bq, bq+16}
        int dq = t >> 4;             // d in {dq, dq+16}
        float a00 = 0.f, a01 = 0.f, a10 = 0.f, a11 = 0.f;
        #pragma unroll 8
        for (int k4 = 0; k4 < 32; k4++) {
            float4 x0 = xs4[bq * 33 + k4];
            float4 x1 = xs4[(bq + 16) * 33 + k4];
            float4 w0 = ws4[dq * 33 + k4];
            float4 w1 = ws4[(dq + 16) * 33 + k4];
            a00 += x0.x * w0.x + x0.y * w0.y + x0.z * w0.z + x0.w * w0.w;
            a01 += x0.x * w1.x + x0.y * w1.y + x0.z * w1.z + x0.w * w1.w;
            a10 += x1.x * w0.x + x1.y * w0.y + x1.z * w0.z + x1.w * w0.w;
            a11 += x1.x * w1.x + x1.y * w1.y + x1.z * w1.z + x1.w * w1.w;
        }
        g_P[(s * BB + bq) * NN + d0 + dq]                = a00;
        g_P[(s * BB + bq) * NN + d0 + dq + 16]           = a01;
        g_P[(s * BB + bq + 16) * NN + d0 + dq]           = a10;
        g_P[(s * BB + bq + 16) * NN + d0 + dq + 16]      = a11;
    }
}

// ---------------- K2: fused step1 closed-form + step2 reduction (128 blocks) ----------------
__global__ void __launch_bounds__(256) k_final(const float* __restrict__ ib) {
    int b  = blockIdx.x;             // batch
    int dqb = blockIdx.y;            // d-quarter
    int t  = threadIdx.x;
    int dl = t & 31;                 // local d
    int iq = t >> 5;                 // 0..7
    int d  = dqb * 32 + dl;
    __shared__ float qs_s[NN], q127_s[NN];
    __shared__ float xt_s[32], s1_s[32];
    __shared__ float pc[8][32], ps[8][32];
    // split-K finalize of x_t for this block's 32 d's
    float xp = 0.f;
    #pragma unroll
    for (int s = iq; s < KSPLIT; s += 8) xp += g_P[(s * BB + b) * NN + d];
    pc[iq][dl] = xp;
    if (t < NN) {
        qs_s[t]   = g_qsum[t];
        q127_s[t] = g_q127[t];
    }
    __syncthreads();
    if (t < 32) {
        float xt = ib[dqb * 32 + t];
        #pragma unroll
        for (int q = 0; q < 8; q++) xt += pc[q][t];
        xt_s[t] = xt;
        s1_s[t] = g_nsum[dqb * 32 + t] + 128.f * xt;
    }
    __syncthreads();
    float xt = xt_s[dl], s1 = s1_s[dl];
    float c = 0.f, ss = 0.f;
    int i0 = iq * 16;
    #pragma unroll
    for (int k = 0; k < 16; k++) {
        int i = i0 + k;
        float v = (g_M0T[i * NN + d] + xt * qs_s[i]) * s1;
        v = (i == d) ? 0.f : fmaxf(v, 0.f);
        c  += v * q127_s[i];
        ss += v;
    }
    pc[iq][dl] = c; ps[iq][dl] = ss;
    __syncthreads();
    if (t < 32) {
        float C = 0.f, S = 0.f;
        #pragma unroll
        for (int q = 0; q < 8; q++) { C += pc[q][t]; S += ps[q][t]; }
        float m = C * S;
        int dd = dqb * 32 + t;
        if (dd == 127) m = 0.f;
        g_out[b * NN + dd] = fmaxf(m, 0.f);
    }
}

// ---------------- K3: recreation GEMM (16-feature tiles, LDS.128 inner loop) + scores ----------------
#define FP 34   // padded row width in float4 (136 floats)
__global__ void __launch_bounds__(256) k_heads(const float* __restrict__ rw,
                                               const float* __restrict__ rb,
                                               const float* __restrict__ sw,
                                               const float* __restrict__ sb,
                                               float* __restrict__ out,
                                               int score_off) {
    int bx = blockIdx.x;
    int t  = threadIdx.x;
    if (bx < 288) {
        __shared__ float4 os4[32 * FP];   // os[b][k], pad 136 floats
        __shared__ float4 ws4[16 * FP];   // ws[f][k], pad 136 floats
        int f0 = bx * 16;
        #pragma unroll
        for (int i = 0; i < 4; i++) {
            int e = t + i * 256;
            int r = e >> 5, c4 = e & 31;
            os4[r * FP + c4] = ((const float4*)&g_out[r * NN])[c4];
        }
        #pragma unroll
        for (int i = 0; i < 2; i++) {
            int e = t + i * 256;
            int r = e >> 5, c4 = e & 31;
            ws4[r * FP + c4] = ((const float4*)&rw[(size_t)(f0 + r) * NN])[c4];
        }
        __syncthreads();
        int bq = t >> 4;          // 0..15 -> batches 2bq, 2bq+1
        int fq = t & 15;          // 0..15 -> feature f0+fq
        float a0 = 0.f, a1 = 0.f;
        const float4* osr0 = &os4[(2 * bq) * FP];
        const float4* osr1 = &os4[(2 * bq + 1) * FP];
        const float4* wsr  = &ws4[fq * FP];
        #pragma unroll
        for (int k4 = 0; k4 < 32; k4++) {
            float4 wv  = wsr[k4];
            float4 x0  = osr0[k4];
            float4 x1  = osr1[k4];
            a0 += x0.x * wv.x + x0.y * wv.y + x0.z * wv.z + x0.w * wv.w;
            a1 += x1.x * wv.x + x1.y * wv.y + x1.z * wv.z + x1.w * wv.w;
        }
        float bias = rb[f0 + fq];
        out[(2 * bq) * INF + f0 + fq]     = a0 + bias;
        out[(2 * bq + 1) * INF + f0 + fq] = a1 + bias;
    } else {
        if (t < BB) {
            float acc = sb[0];
            #pragma unroll 8
            for (int d = 0; d < NN; d++) acc += g_out[t * NN + d] * sw[d];
            out[score_off + t] = acc;
        }
    }
}

// ---------------- launch ----------------
extern "C" void kernel_launch(void* const* d_in, const int* in_sizes, int n_in,
                              void* d_out, int out_size) {
    const float* x   = (const float*)d_in[0];
    const float* ipw = (const float*)d_in[1];
    const float* ipb = (const float*)d_in[2];
    const float* ns  = (const float*)d_in[3];
    const float* ev  = (const float*)d_in[4];
    const float* rw  = (const float*)d_in[5];
    const float* rb  = (const float*)d_in[6];
    const float* sw  = (const float*)d_in[7];
    const float* sb  = (const float*)d_in[8];
    float* out = (float*)d_out;

    k_fused1<<<NN + 1 + 144, 256>>>(ev, ns, x, ipw);
    k_final <<<dim3(BB, 4), 256>>>(ipb);
    k_heads <<<289, 256>>>(rw, rb, sw, sb, out, out_size - BB);
}

// round 16
// speedup vs baseline: 1.0816x; 1.0816x over previous
#include <cuda_runtime.h>

#define NN   128
#define BB   32
#define INF  4608
#define KSPLIT 36    // 4608 / 128
#define KSEG   128

// ---------------- device scratch ----------------
__device__ float g_qsum[NN];              // qsum[i] = sum_n Q[n][i]
__device__ float g_q127[NN];              // q127[n] = Q[n][127]
__device__ float g_nsum[NN];              // nsum[d] = sum_n ns[n][d]
__device__ float g_P[KSPLIT * BB * NN];   // split-K partials of x @ Wt
__device__ float g_Qrow[NN * NN];         // Qrow[i][n] = sum_j ev[i][j][n]
__device__ float g_M0T[NN * NN];          // M0T[i][d] = sum_n Qrow[i][n] ns[n][d]
__device__ float g_out[BB * NN];          // out[b][d]

// ---------------- K1 (fused): ev-reduce -> Qrow/qsum/q127 (tail-free) ; nsum ; input GEMM ----------------
__global__ void __launch_bounds__(256) k_fused1(const float* __restrict__ ev,
                                                const float* __restrict__ ns,
                                                const float* __restrict__ x,
                                                const float* __restrict__ w) {
    int bi = blockIdx.x;
    int t  = threadIdx.x;
    if (bi < NN) {
        // ---- per-i: qv[n] = sum_j ev[i][j][n] (float4 over n); write row, NO tail ----
        __shared__ float4 sred[256];
        int i  = bi;
        int n4 = t & 31;            // float4 index over n (32 x 4 = 128)
        int j0 = t >> 5;            // 0..7
        const float4* p4 = (const float4*)(ev + (size_t)i * NN * NN);  // [128][32]
        float4 a = make_float4(0.f, 0.f, 0.f, 0.f);
        #pragma unroll
        for (int j = j0; j < NN; j += 8) {
            float4 v = p4[j * 32 + n4];
            a.x += v.x; a.y += v.y; a.z += v.z; a.w += v.w;
        }
        sred[t] = a;
        __syncthreads();
        if (j0 < 4) {
            float4 b = sred[t + 128];
            a.x += b.x; a.y += b.y; a.z += b.z; a.w += b.w;
            sred[t] = a;
        }
        __syncthreads();
        if (j0 < 2) {
            float4 b = sred[t + 64];
            a.x += b.x; a.y += b.y; a.z += b.z; a.w += b.w;
            sred[t] = a;
        }
        __syncthreads();
        if (j0 == 0) {
            float4 b = sred[t + 32];
            a.x += b.x; a.y += b.y; a.z += b.z; a.w += b.w;
            ((float4*)g_Qrow)[i * 32 + n4] = a;            // Qrow[i][n]
            if (i == 127) ((float4*)g_q127)[n4] = a;       // q127[n] = Q[n][127]
            float s = a.x + a.y + a.z + a.w;
            #pragma unroll
            for (int off = 16; off > 0; off >>= 1)
                s += __shfl_xor_sync(0xffffffffu, s, off);
            if (n4 == 0) g_qsum[i] = s;
        }
    } else if (bi == NN) {
        // ---- nsum[d] = sum_n ns[n][d] ----
        if (t < NN) {
            float acc = 0.f;
            #pragma unroll 16
            for (int n = 0; n < NN; n++) acc += ns[n * NN + t];
            g_nsum[t] = acc;
        }
    } else {
        // ---- input GEMM split-K (R9 form): idx in [0,144) -> (s, db) ----
        __shared__ float xs[32 * 129];
        __shared__ float ws[32 * 129];
        int idx = bi - NN - 1;
        int s   = idx >> 2;          // 0..35
        int db  = idx & 3;           // 0..3
        int k0  = s * KSEG;
        int d0  = db * 32;
        #pragma unroll
        for (int it = 0; it < 4; it++) {
            int e  = t + it * 256;
            int r  = e >> 5, c4 = e & 31;
            float4 xv = *(const float4*)&x[r * INF + k0 + c4 * 4];
            float4 wv = *(const float4*)&w[(d0 + r) * INF + k0 + c4 * 4];
            int o = r * 129 + c4 * 4;
            xs[o + 0] = xv.x; xs[o + 1] = xv.y; xs[o + 2] = xv.z; xs[o + 3] = xv.w;
            ws[o + 0] = wv.x; ws[o + 1] = wv.y; ws[o + 2] = wv.z; ws[o + 3] = wv.w;
        }
        __syncthreads();
        int bq = t & 15, dq = t >> 4;
        float a00 = 0.f, a01 = 0.f, a10 = 0.f, a11 = 0.f;
        #pragma unroll 8
        for (int k = 0; k < KSEG; k++) {
            float xb0 = xs[(2 * bq) * 129 + k];
            float xb1 = xs[(2 * bq + 1) * 129 + k];
            float wd0 = ws[(2 * dq) * 129 + k];
            float wd1 = ws[(2 * dq + 1) * 129 + k];
            a00 += xb0 * wd0; a01 += xb0 * wd1;
            a10 += xb1 * wd0; a11 += xb1 * wd1;
        }
        int b0 = 2 * bq, dl = 2 * dq;
        g_P[(s * BB + b0) * NN + d0 + dl]           = a00;
        g_P[(s * BB + b0) * NN + d0 + dl + 1]       = a01;
        g_P[(s * BB + b0 + 1) * NN + d0 + dl]       = a10;
        g_P[(s * BB + b0 + 1) * NN + d0 + dl + 1]   = a11;
    }
}

// ---------------- K2: M0T[i][d] = sum_n Qrow[i][n] * ns[n][d] (2 MMAC GEMM, L2-hot) ----------------
__global__ void __launch_bounds__(256) k_M0(const float* __restrict__ ns) {
    __shared__ float Qs[NN * 33];   // Qs[n][il]  (transposed during load)
    __shared__ float Ns[NN * 33];   // Ns[n][dl]
    int i0 = blockIdx.x * 32;
    int d0 = blockIdx.y * 32;
    int t  = threadIdx.x;
    // load Q tile [32 i][128 n] coalesced, store transposed
    #pragma unroll
    for (int rep = 0; rep < 4; rep++) {
        int e  = t + rep * 256;        // 0..1023 float4
        int il = e >> 5, c4 = e & 31;
        float4 v = ((const float4*)g_Qrow)[(i0 + il) * 32 + c4];
        Qs[(4 * c4 + 0) * 33 + il] = v.x;
        Qs[(4 * c4 + 1) * 33 + il] = v.y;
        Qs[(4 * c4 + 2) * 33 + il] = v.z;
        Qs[(4 * c4 + 3) * 33 + il] = v.w;
    }
    // load ns strip [128 n][32 d]
    #pragma unroll
    for (int rep = 0; rep < 4; rep++) {
        int e  = t + rep * 256;        // 0..1023 float4 (4096 floats)
        int n  = e >> 3, c4 = e & 7;
        float4 v = *(const float4*)&ns[n * NN + d0 + c4 * 4];
        Ns[n * 33 + 4 * c4 + 0] = v.x;
        Ns[n * 33 + 4 * c4 + 1] = v.y;
        Ns[n * 33 + 4 * c4 + 2] = v.z;
        Ns[n * 33 + 4 * c4 + 3] = v.w;
    }
    __syncthreads();
    int tx = t & 15, ty = t >> 4;
    int dl = 2 * tx, il = 2 * ty;
    float a00 = 0.f, a01 = 0.f, a10 = 0.f, a11 = 0.f;
    #pragma unroll 8
    for (int n = 0; n < NN; n++) {
        float q0 = Qs[n * 33 + il], q1 = Qs[n * 33 + il + 1];
        float s0 = Ns[n * 33 + dl], s1 = Ns[n * 33 + dl + 1];
        a00 += q0 * s0; a01 += q0 * s1;
        a10 += q1 * s0; a11 += q1 * s1;
    }
    g_M0T[(i0 + il) * NN + d0 + dl]           = a00;
    g_M0T[(i0 + il) * NN + d0 + dl + 1]       = a01;
    g_M0T[(i0 + il + 1) * NN + d0 + dl]       = a10;
    g_M0T[(i0 + il + 1) * NN + d0 + dl + 1]   = a11;
}

// ---------------- K3: fused step1 closed-form + step2 reduction (8-way i-split) ----------------
__global__ void __launch_bounds__(1024) k_final(const float* __restrict__ ib) {
    int b  = blockIdx.x;
    int t  = threadIdx.x;
    int d  = t & 127;
    int iq = t >> 7;                 // 0..7
    __shared__ float qs_s[NN], q127_s[NN], xt_s[NN], s1_s[NN];
    __shared__ float pc[8][NN], ps[8][NN];
    float xp = 0.f;
    #pragma unroll
    for (int s = iq; s < KSPLIT; s += 8) xp += g_P[(s * BB + b) * NN + d];
    pc[iq][d] = xp;
    if (t < NN) {
        qs_s[t]   = g_qsum[t];
        q127_s[t] = g_q127[t];
    }
    __syncthreads();
    if (t < NN) {
        float xt = ib[t];
        #pragma unroll
        for (int q = 0; q < 8; q++) xt += pc[q][t];
        xt_s[t] = xt;
        s1_s[t] = g_nsum[t] + 128.f * xt;
    }
    __syncthreads();
    float xt = xt_s[d], s1 = s1_s[d];
    float c = 0.f, ss = 0.f;
    int i0 = iq * 16;
    #pragma unroll
    for (int k = 0; k < 16; k++) {
        int i = i0 + k;
        float v = (g_M0T[i * NN + d] + xt * qs_s[i]) * s1;
        v = (i == d) ? 0.f : fmaxf(v, 0.f);
        c  += v * q127_s[i];
        ss += v;
    }
    pc[iq][d] = c; ps[iq][d] = ss;
    __syncthreads();
    if (t < NN) {
        float C = 0.f, S = 0.f;
        #pragma unroll
        for (int q = 0; q < 8; q++) { C += pc[q][d]; S += ps[q][d]; }
        float m = C * S;
        if (d == 127) m = 0.f;
        g_out[b * NN + d] = fmaxf(m, 0.f);
    }
}

// ---------------- K4: recreation GEMM (16-feature tiles, LDS.128 inner loop) + scores ----------------
#define FP 34   // padded row width in float4 (136 floats)
__global__ void __launch_bounds__(256) k_heads(const float* __restrict__ rw,
                                               const float* __restrict__ rb,
                                               const float* __restrict__ sw,
                                               const float* __restrict__ sb,
                                               float* __restrict__ out,
                                               int score_off) {
    int bx = blockIdx.x;
    int t  = threadIdx.x;
    if (bx < 288) {
        __shared__ float4 os4[32 * FP];   // os[b][k], pad 136 floats
        __shared__ float4 ws4[16 * FP];   // ws[f][k], pad 136 floats
        int f0 = bx * 16;
        #pragma unroll
        for (int i = 0; i < 4; i++) {
            int e = t + i * 256;
            int r = e >> 5, c4 = e & 31;
            os4[r * FP + c4] = ((const float4*)&g_out[r * NN])[c4];
        }
        #pragma unroll
        for (int i = 0; i < 2; i++) {
            int e = t + i * 256;
            int r = e >> 5, c4 = e & 31;
            ws4[r * FP + c4] = ((const float4*)&rw[(size_t)(f0 + r) * NN])[c4];
        }
        __syncthreads();
        int bq = t >> 4;          // 0..15 -> batches 2bq, 2bq+1
        int fq = t & 15;          // 0..15 -> feature f0+fq
        float a0 = 0.f, a1 = 0.f;
        const float4* osr0 = &os4[(2 * bq) * FP];
        const float4* osr1 = &os4[(2 * bq + 1) * FP];
        const float4* wsr  = &ws4[fq * FP];
        #pragma unroll
        for (int k4 = 0; k4 < 32; k4++) {
            float4 wv  = wsr[k4];
            float4 x0  = osr0[k4];
            float4 x1  = osr1[k4];
            a0 += x0.x * wv.x + x0.y * wv.y + x0.z * wv.z + x0.w * wv.w;
            a1 += x1.x * wv.x + x1.y * wv.y + x1.z * wv.z + x1.w * wv.w;
        }
        float bias = rb[f0 + fq];
        out[(2 * bq) * INF + f0 + fq]     = a0 + bias;
        out[(2 * bq + 1) * INF + f0 + fq] = a1 + bias;
    } else {
        if (t < BB) {
            float acc = sb[0];
            #pragma unroll 8
            for (int d = 0; d < NN; d++) acc += g_out[t * NN + d] * sw[d];
            out[score_off + t] = acc;
        }
    }
}

// ---------------- launch ----------------
extern "C" void kernel_launch(void* const* d_in, const int* in_sizes, int n_in,
                              void* d_out, int out_size) {
    const float* x   = (const float*)d_in[0];
    const float* ipw = (const float*)d_in[1];
    const float* ipb = (const float*)d_in[2];
    const float* ns  = (const float*)d_in[3];
    const float* ev  = (const float*)d_in[4];
    const float* rw  = (const float*)d_in[5];
    const float* rb  = (const float*)d_in[6];
    const float* sw  = (const float*)d_in[7];
    const float* sb  = (const float*)d_in[8];
    float* out = (float*)d_out;

    k_fused1<<<NN + 1 + 144, 256>>>(ev, ns, x, ipw);
    k_M0    <<<dim3(4, 4), 256>>>(ns);
    k_final <<<BB, 1024>>>(ipb);
    k_heads <<<289, 256>>>(rw, rb, sw, sb, out, out_size - BB);
}

// round 17
// speedup vs baseline: 1.2790x; 1.1825x over previous
#include <cuda_runtime.h>

#define NN   128
#define BB   32
#define INF  4608
#define KSPLIT 36    // 4608 / 128
#define KSEG   128

// ---------------- device scratch ----------------
__device__ float g_qsum[NN];              // qsum[i] = sum_n Q[n][i]
__device__ float g_q127[NN];              // q127[n] = Q[n][127]
__device__ float g_nsum[NN];              // nsum[d] = sum_n ns[n][d]
__device__ float g_P[KSPLIT * BB * NN];   // split-K partials of x @ Wt
__device__ float g_M0T[NN * NN];          // M0T[i][d] = sum_n ns[n][d] Q[n][i]
__device__ float g_out[BB * NN];          // out[b][d]

// ---------------- K1 (fused): ev-reduce -> qsum/q127/M0T ; nsum ; input GEMM ----------------
__global__ void __launch_bounds__(256) k_fused1(const float* __restrict__ ev,
                                                const float* __restrict__ ns,
                                                const float* __restrict__ x,
                                                const float* __restrict__ w) {
    int bi = blockIdx.x;
    int t  = threadIdx.x;
    if (bi < NN) {
        // ---- per-i: qv[n] = Q[n][i] = sum_j ev[i][j][n] (float4 over n) ----
        __shared__ float4 sred[256];
        __shared__ float  qsh[NN];
        __shared__ float  pd[256];
        int i  = bi;
        int n4 = t & 31;            // float4 index over n (32 x 4 = 128)
        int j0 = t >> 5;            // 0..7
        const float4* p4 = (const float4*)(ev + (size_t)i * NN * NN);  // [128][32]
        float4 a = make_float4(0.f, 0.f, 0.f, 0.f);
        #pragma unroll
        for (int j = j0; j < NN; j += 8) {
            float4 v = p4[j * 32 + n4];
            a.x += v.x; a.y += v.y; a.z += v.z; a.w += v.w;
        }
        sred[t] = a;
        __syncthreads();
        if (j0 < 4) {
            float4 b = sred[t + 128];
            a.x += b.x; a.y += b.y; a.z += b.z; a.w += b.w;
            sred[t] = a;
        }
        __syncthreads();
        if (j0 < 2) {
            float4 b = sred[t + 64];
            a.x += b.x; a.y += b.y; a.z += b.z; a.w += b.w;
            sred[t] = a;
        }
        __syncthreads();
        if (j0 == 0) {
            float4 b = sred[t + 32];
            a.x += b.x; a.y += b.y; a.z += b.z; a.w += b.w;
            qsh[4 * n4 + 0] = a.x; qsh[4 * n4 + 1] = a.y;
            qsh[4 * n4 + 2] = a.z; qsh[4 * n4 + 3] = a.w;
            if (i == 127) ((float4*)g_q127)[n4] = a;       // Q[n][127]
            float s = a.x + a.y + a.z + a.w;
            #pragma unroll
            for (int off = 16; off > 0; off >>= 1)
                s += __shfl_xor_sync(0xffffffffu, s, off);
            if (n4 == 0) g_qsum[i] = s;
        }
        __syncthreads();
        // M0T[i][d] = sum_n qsh[n] * ns[n][d]  (split n across 2 halves)
        int d = t & 127, h = t >> 7;
        float m = 0.f;
        int nb = h * 64;
        #pragma unroll 8
        for (int k = 0; k < 64; k++) m += qsh[nb + k] * ns[(nb + k) * NN + d];
        pd[t] = m;
        __syncthreads();
        if (t < NN) g_M0T[i * NN + t] = pd[t] + pd[t + 128];
    } else if (bi == NN) {
        // ---- nsum[d] = sum_n ns[n][d] ----
        if (t < NN) {
            float acc = 0.f;
            #pragma unroll 16
            for (int n = 0; n < NN; n++) acc += ns[n * NN + t];
            g_nsum[t] = acc;
        }
    } else {
        // ---- input GEMM split-K: idx in [0,144) -> (s, db); single-phase 128-k tile ----
        __shared__ float xs[32 * 129];
        __shared__ float ws[32 * 129];
        int idx = bi - NN - 1;
        int s   = idx >> 2;          // 0..35
        int db  = idx & 3;           // 0..3
        int k0  = s * KSEG;
        int d0  = db * 32;
        #pragma unroll
        for (int it = 0; it < 4; it++) {
            int e  = t + it * 256;
            int r  = e >> 5, c4 = e & 31;
            float4 xv = *(const float4*)&x[r * INF + k0 + c4 * 4];
            float4 wv = *(const float4*)&w[(d0 + r) * INF + k0 + c4 * 4];
            int o = r * 129 + c4 * 4;
            xs[o + 0] = xv.x; xs[o + 1] = xv.y; xs[o + 2] = xv.z; xs[o + 3] = xv.w;
            ws[o + 0] = wv.x; ws[o + 1] = wv.y; ws[o + 2] = wv.z; ws[o + 3] = wv.w;
        }
        __syncthreads();
        int bq = t & 15, dq = t >> 4;
        float a00 = 0.f, a01 = 0.f, a10 = 0.f, a11 = 0.f;
        #pragma unroll 8
        for (int k = 0; k < KSEG; k++) {
            float xb0 = xs[(2 * bq) * 129 + k];
            float xb1 = xs[(2 * bq + 1) * 129 + k];
            float wd0 = ws[(2 * dq) * 129 + k];
            float wd1 = ws[(2 * dq + 1) * 129 + k];
            a00 += xb0 * wd0; a01 += xb0 * wd1;
            a10 += xb1 * wd0; a11 += xb1 * wd1;
        }
        int b0 = 2 * bq, dl = 2 * dq;
        g_P[(s * BB + b0) * NN + d0 + dl]           = a00;
        g_P[(s * BB + b0) * NN + d0 + dl + 1]       = a01;
        g_P[(s * BB + b0 + 1) * NN + d0 + dl]       = a10;
        g_P[(s * BB + b0 + 1) * NN + d0 + dl + 1]   = a11;
    }
}

// ---------------- K2: fused step1 closed-form + step2 reduction + scores ----------------
__global__ void __launch_bounds__(1024) k_final(const float* __restrict__ ib,
                                                const float* __restrict__ sw,
                                                const float* __restrict__ sb,
                                                float* __restrict__ out,
                                                int score_off) {
    int b  = blockIdx.x;
    int t  = threadIdx.x;
    int d  = t & 127;
    int iq = t >> 7;                 // 0..7
    __shared__ float qs_s[NN], q127_s[NN], xt_s[NN], s1_s[NN];
    __shared__ float pc[8][NN], ps[8][NN];
    float xp = 0.f;
    #pragma unroll
    for (int s = iq; s < KSPLIT; s += 8) xp += g_P[(s * BB + b) * NN + d];
    pc[iq][d] = xp;
    if (t < NN) {
        qs_s[t]   = g_qsum[t];
        q127_s[t] = g_q127[t];
    }
    __syncthreads();
    if (t < NN) {
        float xt = ib[t];
        #pragma unroll
        for (int q = 0; q < 8; q++) xt += pc[q][t];
        xt_s[t] = xt;
        s1_s[t] = g_nsum[t] + 128.f * xt;
    }
    __syncthreads();
    float xt = xt_s[d], s1 = s1_s[d];
    float c = 0.f, ss = 0.f;
    int i0 = iq * 16;
    #pragma unroll
    for (int k = 0; k < 16; k++) {
        int i = i0 + k;
        float v = (g_M0T[i * NN + d] + xt * qs_s[i]) * s1;
        v = (i == d) ? 0.f : fmaxf(v, 0.f);
        c  += v * q127_s[i];
        ss += v;
    }
    pc[iq][d] = c; ps[iq][d] = ss;
    __syncthreads();
    if (t < NN) {
        float C = 0.f, S = 0.f;
        #pragma unroll
        for (int q = 0; q < 8; q++) { C += pc[q][d]; S += ps[q][d]; }
        float m = C * S;
        if (d == 127) m = 0.f;
        float val = fmaxf(m, 0.f);
        g_out[b * NN + d] = val;
        s1_s[d] = val * sw[d];       // partial product for the score dot
    }
    __syncthreads();
    if (t < 32) {
        float acc = s1_s[t] + s1_s[t + 32] + s1_s[t + 64] + s1_s[t + 96];
        #pragma unroll
        for (int off = 16; off > 0; off >>= 1)
            acc += __shfl_xor_sync(0xffffffffu, acc, off);
        if (t == 0) out[score_off + b] = acc + sb[0];
    }
}

// ---------------- K3: recreation GEMM (16-feature tiles, LDS.128 inner loop) ----------------
#define FP 34   // padded row width in float4 (136 floats)
__global__ void __launch_bounds__(256) k_heads(const float* __restrict__ rw,
                                               const float* __restrict__ rb,
                                               float* __restrict__ out) {
    int bx = blockIdx.x;
    int t  = threadIdx.x;
    __shared__ float4 os4[32 * FP];   // os[b][k], pad 136 floats
    __shared__ float4 ws4[16 * FP];   // ws[f][k], pad 136 floats
    int f0 = bx * 16;
    #pragma unroll
    for (int i = 0; i < 4; i++) {
        int e = t + i * 256;
        int r = e >> 5, c4 = e & 31;
        os4[r * FP + c4] = ((const float4*)&g_out[r * NN])[c4];
    }
    #pragma unroll
    for (int i = 0; i < 2; i++) {
        int e = t + i * 256;
        int r = e >> 5, c4 = e & 31;
        ws4[r * FP + c4] = ((const float4*)&rw[(size_t)(f0 + r) * NN])[c4];
    }
    __syncthreads();
    int bq = t >> 4;          // 0..15 -> batches 2bq, 2bq+1
    int fq = t & 15;          // 0..15 -> feature f0+fq
    float a0 = 0.f, a1 = 0.f;
    const float4* osr0 = &os4[(2 * bq) * FP];
    const float4* osr1 = &os4[(2 * bq + 1) * FP];
    const float4* wsr  = &ws4[fq * FP];
    #pragma unroll
    for (int k4 = 0; k4 < 32; k4++) {
        float4 wv  = wsr[k4];
        float4 x0  = osr0[k4];
        float4 x1  = osr1[k4];
        a0 += x0.x * wv.x + x0.y * wv.y + x0.z * wv.z + x0.w * wv.w;
        a1 += x1.x * wv.x + x1.y * wv.y + x1.z * wv.z + x1.w * wv.w;
    }
    float bias = rb[f0 + fq];
    out[(2 * bq) * INF + f0 + fq]     = a0 + bias;
    out[(2 * bq + 1) * INF + f0 + fq] = a1 + bias;
}

// ---------------- launch ----------------
extern "C" void kernel_launch(void* const* d_in, const int* in_sizes, int n_in,
                              void* d_out, int out_size) {
    const float* x   = (const float*)d_in[0];
    const float* ipw = (const float*)d_in[1];
    const float* ipb = (const float*)d_in[2];
    const float* ns  = (const float*)d_in[3];
    const float* ev  = (const float*)d_in[4];
    const float* rw  = (const float*)d_in[5];
    const float* rb  = (const float*)d_in[6];
    const float* sw  = (const float*)d_in[7];
    const float* sb  = (const float*)d_in[8];
    float* out = (float*)d_out;

    k_fused1<<<NN + 1 + 144, 256>>>(ev, ns, x, ipw);
    k_final <<<BB, 1024>>>(ipb, sw, sb, out, out_size - BB);
    k_heads <<<288, 256>>>(rw, rb, out);
}